// round 14
// baseline (speedup 1.0000x reference)
#include <cuda_runtime.h>
#include <cuda_fp16.h>
#include <cstdint>

#define D 64
#define KTOT 2048
#define MTILE 128
#define NCHUNK 128
#define NCHUNKS (KTOT / NCHUNK)   // 16
#define TPB 128                   // 4 warps, each owns an m32 slab

#define SAH 72            // A fp16 plane row stride (fp16 elems; 144 B = 9*16, ldmatrix-aligned)
#define SBROW 132         // B smem row stride in uint2 (1056 B)

#define OFF_AH 0
#define AH_BYTES (MTILE * SAH * 2)                // 18432
#define OFF_AL AH_BYTES                           // 18432
#define OFF_B0 (2 * AH_BYTES)                     // 36864
#define B_BYTES (32 * SBROW * 8)                  // 33792
#define OFF_B1 (OFF_B0 + B_BYTES)                 // 70656
#define OFF_HN (OFF_B1 + B_BYTES)                 // 104448
#define OFF_BK (OFF_HN + KTOT * 4)                // 112640
#define SMEM_TOTAL (OFF_BK + MTILE * 4)           // 113152

// ---------------- device scratch (no runtime allocation) ----------------
__device__ float g_halfnorm[KTOT];
// [chunk][kpair(32)][n(128)] -> (h0|h1<<16, l0|l1<<16)
__device__ __align__(16) uint2 g_bsplit[NCHUNKS * 32 * NCHUNK];

// ---------------- helpers ----------------
__device__ __forceinline__ uint32_t smem_u32(const void* p) {
    uint32_t a;
    asm("{ .reg .u64 t; cvta.to.shared.u64 t, %1; cvt.u32.u64 %0, t; }" : "=r"(a) : "l"(p));
    return a;
}
__device__ __forceinline__ void split_f16(float x, uint16_t& h, uint16_t& l) {
    __half hh = __float2half_rn(x);
    __half ll = __float2half_rn(x - __half2float(hh));
    h = __half_as_ushort(hh);
    l = __half_as_ushort(ll);
}
__device__ __forceinline__ void mma_f16(float& c0, float& c1, float& c2, float& c3,
                                        uint32_t a0, uint32_t a1, uint32_t a2, uint32_t a3,
                                        uint32_t b0, uint32_t b1) {
    asm volatile(
        "mma.sync.aligned.m16n8k16.row.col.f32.f16.f16.f32 "
        "{%0,%1,%2,%3}, {%4,%5,%6,%7}, {%8,%9}, {%0,%1,%2,%3};"
        : "+f"(c0), "+f"(c1), "+f"(c2), "+f"(c3)
        : "r"(a0), "r"(a1), "r"(a2), "r"(a3), "r"(b0), "r"(b1));
}
__device__ __forceinline__ void ldsm_x4(uint32_t& r0, uint32_t& r1, uint32_t& r2, uint32_t& r3,
                                        uint32_t addr) {
    asm volatile("ldmatrix.sync.aligned.m8n8.x4.shared.b16 {%0,%1,%2,%3}, [%4];"
                 : "=r"(r0), "=r"(r1), "=r"(r2), "=r"(r3) : "r"(addr));
}
#define CP_ASYNC16(dst, src) \
    asm volatile("cp.async.cg.shared.global [%0], [%1], 16;" :: "r"(dst), "l"(src) : "memory")
#define CP_COMMIT() asm volatile("cp.async.commit_group;" ::: "memory")
#define CP_WAIT1()  asm volatile("cp.async.wait_group 1;" ::: "memory")

// ---------------- fused prep kernel (halfnorm + fp16 h/l split) ----------------
__global__ void prep_kernel(const float* __restrict__ c) {
    int kc = blockIdx.x * blockDim.x + threadIdx.x;   // one centroid per thread
    if (kc >= KTOT) return;
    const int chunk = kc >> 7, n = kc & 127;
    uint2* dst = g_bsplit + chunk * (32 * NCHUNK) + n;
    float s = 0.f;
#pragma unroll
    for (int i = 0; i < D / 4; i++) {
        float4 v = ((const float4*)(c + (size_t)kc * D))[i];
        s += v.x * v.x + v.y * v.y + v.z * v.z + v.w * v.w;
        uint16_t h0, l0, h1, l1, h2, l2, h3, l3;
        split_f16(v.x, h0, l0); split_f16(v.y, h1, l1);
        split_f16(v.z, h2, l2); split_f16(v.w, h3, l3);
        dst[(2 * i) * NCHUNK]     = make_uint2((uint32_t)h0 | ((uint32_t)h1 << 16),
                                               (uint32_t)l0 | ((uint32_t)l1 << 16));
        dst[(2 * i + 1) * NCHUNK] = make_uint2((uint32_t)h2 | ((uint32_t)h3 << 16),
                                               (uint32_t)l2 | ((uint32_t)l3 << 16));
    }
    g_halfnorm[kc] = 0.5f * s;
}

// ---------------- main kernel ----------------
__device__ __forceinline__ void prefetch_chunk(uint32_t sbm, int buf, int ch, int tid) {
    // 32 rows x 128 uint2 = 32 KB = 2048 x 16B
    const char* src = (const char*)g_bsplit + (size_t)ch * 32768;
#pragma unroll
    for (int i = 0; i < 16; i++) {
        int idx = tid + i * TPB;           // 0..2047
        int r = idx >> 6, u = idx & 63;
        uint32_t dst = sbm + (buf ? OFF_B1 : OFF_B0) + r * (SBROW * 8) + u * 16;
        CP_ASYNC16(dst, src + r * 1024 + u * 16);
    }
}

template <int OutMode>
__global__ __launch_bounds__(TPB, 2) void vq_mma_kernel(
    const float* __restrict__ action, const float* __restrict__ centroids,
    void* __restrict__ out, int N) {
    extern __shared__ char smem[];
    const uint32_t sbm = smem_u32(smem);
    const int tid = threadIdx.x;
    const int w = tid >> 5;      // warp 0..3, owns rows [w*32, w*32+32)
    const int lane = tid & 31;
    const int g = lane >> 2;     // group id 0..7
    const int t = lane & 3;      // thread-in-group 0..3

    prefetch_chunk(sbm, 0, 0, tid);
    CP_COMMIT();
    prefetch_chunk(sbm, 1, 1, tid);
    CP_COMMIT();

    // stage A tile [128][64]: split fp32 -> fp16 h/l planes (stride SAH fp16)
    {
        const float4* src = (const float4*)(action + (size_t)blockIdx.x * MTILE * D);
#pragma unroll
        for (int i = 0; i < 16; i++) {
            int idx = tid + i * TPB;           // 2048 float4
            int r = idx >> 4, c4 = idx & 15;   // row, group of 4 cols
            float4 v = src[idx];
            uint16_t h0, l0, h1, l1, h2, l2, h3, l3;
            split_f16(v.x, h0, l0); split_f16(v.y, h1, l1);
            split_f16(v.z, h2, l2); split_f16(v.w, h3, l3);
            uint32_t off = (uint32_t)r * (SAH * 2) + (uint32_t)c4 * 8;
            *(uint2*)(smem + OFF_AH + off) =
                make_uint2((uint32_t)h0 | ((uint32_t)h1 << 16),
                           (uint32_t)h2 | ((uint32_t)h3 << 16));
            *(uint2*)(smem + OFF_AL + off) =
                make_uint2((uint32_t)l0 | ((uint32_t)l1 << 16),
                           (uint32_t)l2 | ((uint32_t)l3 << 16));
        }
    }
    // stage halfnorms
    {
        const float4* src = (const float4*)g_halfnorm;
#pragma unroll
        for (int i = 0; i < 4; i++) {
            int idx = tid + i * TPB;
            *(float4*)(smem + OFF_HN + idx * 16) = src[idx];
        }
    }
    __syncthreads();

    // ldmatrix base addresses (per s-slab, per plane); advance by 32B per ks.
    const int arow = w * 32 + (lane & 15);
    const uint32_t acol8 = ((lane >> 4) & 1) * 16;   // +8 fp16 = 16 B
    uint32_t aaddr[2][2];                            // [s][plane]
#pragma unroll
    for (int s = 0; s < 2; s++) {
        uint32_t rowoff = (uint32_t)(arow + s * 16) * (SAH * 2) + acol8;
        aaddr[s][0] = sbm + OFF_AH + rowoff;
        aaddr[s][1] = sbm + OFF_AL + rowoff;
    }

    // best per thread for rows w*32 + g + {0, 8, 16, 24}
    float best[4];
    int bk[4];
#pragma unroll
    for (int j = 0; j < 4; j++) { best[j] = -3.402823466e38f; bk[j] = 0; }

    const uint32_t browoff = (uint32_t)(t * SBROW + g) * 8;   // (kpair=t, n=g)

    for (int ch = 0; ch < NCHUNKS; ch++) {
        CP_WAIT1();
        __syncthreads();
        const char* bbase = (const char*)smem + ((ch & 1) ? OFF_B1 : OFF_B0) + browoff;
        const float* hn = (const float*)(smem + OFF_HN) + ch * NCHUNK;

#pragma unroll
        for (int ng = 0; ng < 4; ng++) {
            // single accumulator set: hh + h*l + l*h all accumulate here (fp32)
            float acc[4][8];
#pragma unroll
            for (int q = 0; q < 4; q++) {
                const int na = ng * 32 + q * 8 + 2 * t;
                const float h0 = hn[na], h1 = hn[na + 1];
#pragma unroll
                for (int s = 0; s < 2; s++) {
                    acc[q][s * 4 + 0] = -h0;
                    acc[q][s * 4 + 1] = -h1;
                    acc[q][s * 4 + 2] = -h0;
                    acc[q][s * 4 + 3] = -h1;
                }
            }

#pragma unroll
            for (int ks = 0; ks < 4; ks++) {
                // A fragments for this k-step via ldmatrix (h and l, both slabs)
                uint32_t ah[2][4], al[2][4];
#pragma unroll
                for (int s = 0; s < 2; s++) {
                    ldsm_x4(ah[s][0], ah[s][1], ah[s][2], ah[s][3], aaddr[s][0] + ks * 32);
                    ldsm_x4(al[s][0], al[s][1], al[s][2], al[s][3], aaddr[s][1] + ks * 32);
                }
                uint2 u0[4], u1[4];
#pragma unroll
                for (int q = 0; q < 4; q++) {
                    const char* p0 = bbase + (uint32_t)ks * (8 * SBROW * 8) +
                                     (uint32_t)(ng * 32 + q * 8) * 8;
                    u0[q] = *(const uint2*)p0;                      // kpair 8ks+t
                    u1[q] = *(const uint2*)(p0 + 4 * SBROW * 8);    // kpair 8ks+t+4
                }
#pragma unroll
                for (int q = 0; q < 4; q++) {
#pragma unroll
                    for (int s = 0; s < 2; s++) {
                        mma_f16(acc[q][s*4+0], acc[q][s*4+1], acc[q][s*4+2], acc[q][s*4+3],
                                ah[s][0], ah[s][1], ah[s][2], ah[s][3], u0[q].x, u1[q].x);
                        mma_f16(acc[q][s*4+0], acc[q][s*4+1], acc[q][s*4+2], acc[q][s*4+3],
                                ah[s][0], ah[s][1], ah[s][2], ah[s][3], u0[q].y, u1[q].y);
                        mma_f16(acc[q][s*4+0], acc[q][s*4+1], acc[q][s*4+2], acc[q][s*4+3],
                                al[s][0], al[s][1], al[s][2], al[s][3], u0[q].x, u1[q].x);
                    }
                }
            }

            // argmax update (ascending n => strict '>' keeps earliest index)
#pragma unroll
            for (int q = 0; q < 4; q++) {
                const int na = ng * 32 + q * 8 + 2 * t;
                const int base = ch * NCHUNK;
#pragma unroll
                for (int s = 0; s < 2; s++) {
                    float s0 = acc[q][s*4+0];   // (row g+s*16,   na)
                    float s1 = acc[q][s*4+1];   // (row g+s*16,   na+1)
                    float s2 = acc[q][s*4+2];   // (row g+s*16+8, na)
                    float s3 = acc[q][s*4+3];   // (row g+s*16+8, na+1)
                    if (s0 > best[s*2+0]) { best[s*2+0] = s0; bk[s*2+0] = base + na; }
                    if (s1 > best[s*2+0]) { best[s*2+0] = s1; bk[s*2+0] = base + na + 1; }
                    if (s2 > best[s*2+1]) { best[s*2+1] = s2; bk[s*2+1] = base + na; }
                    if (s3 > best[s*2+1]) { best[s*2+1] = s3; bk[s*2+1] = base + na + 1; }
                }
            }
        }

        __syncthreads();
        {
            const int nxt = ch + 2;
            if (nxt < NCHUNKS) prefetch_chunk(sbm, nxt & 1, nxt, tid);
            CP_COMMIT();
        }
    }

    // quad reduction (over t), earliest index on ties
#pragma unroll
    for (int off = 1; off < 4; off <<= 1) {
#pragma unroll
        for (int j = 0; j < 4; j++) {
            float ob = __shfl_xor_sync(0xffffffffu, best[j], off);
            int ok = __shfl_xor_sync(0xffffffffu, bk[j], off);
            if (ob > best[j] || (ob == best[j] && ok < bk[j])) { best[j] = ob; bk[j] = ok; }
        }
    }
    if (t == 0) {
        int* sb = (int*)(smem + OFF_BK);
        sb[w * 32 + g]      = bk[0];
        sb[w * 32 + g + 8]  = bk[1];
        sb[w * 32 + g + 16] = bk[2];
        sb[w * 32 + g + 24] = bk[3];
    }
    __syncthreads();

    // epilogue (reload A from gmem; residual = a - c_best)
    const int* sbk = (const int*)(smem + OFF_BK);
    const int pbase = blockIdx.x * MTILE;
    const float4* asrc = (const float4*)(action + (size_t)pbase * D);
    if (OutMode == 1) {
        if (tid < MTILE) ((long long*)out)[pbase + tid] = (long long)sbk[tid];
        float* rbase = (float*)out + 2 * (size_t)N;
#pragma unroll
        for (int i = 0; i < 16; i++) {
            int idx = tid + i * TPB;
            int row = idx >> 4, c4 = idx & 15;
            float4 a = asrc[idx];
            float4 c = ((const float4*)(centroids + (size_t)sbk[row] * D))[c4];
            ((float4*)(rbase + (size_t)(pbase + row) * D))[c4] =
                make_float4(a.x - c.x, a.y - c.y, a.z - c.z, a.w - c.w);
        }
    } else {
        float* o = (float*)out;
        if (tid < MTILE) o[pbase + tid] = (float)sbk[tid];   // exact for K<=2048
        float* rbase = o + (size_t)N;
#pragma unroll
        for (int i = 0; i < 16; i++) {
            int idx = tid + i * TPB;
            int row = idx >> 4, c4 = idx & 15;
            float4 a = asrc[idx];
            float4 c = ((const float4*)(centroids + (size_t)sbk[row] * D))[c4];
            ((float4*)(rbase + (size_t)(pbase + row) * D))[c4] =
                make_float4(a.x - c.x, a.y - c.y, a.z - c.z, a.w - c.w);
        }
    }
}

// ---------------- launch ----------------
extern "C" void kernel_launch(void* const* d_in, const int* in_sizes, int n_in,
                              void* d_out, int out_size) {
    const float* action = (const float*)d_in[0];
    const float* centroids = (const float*)d_in[1];
    const int N = in_sizes[0] / D;   // 65536

    cudaFuncSetAttribute(vq_mma_kernel<0>, cudaFuncAttributeMaxDynamicSharedMemorySize, SMEM_TOTAL);
    cudaFuncSetAttribute(vq_mma_kernel<1>, cudaFuncAttributeMaxDynamicSharedMemorySize, SMEM_TOTAL);

    prep_kernel<<<(KTOT + 127) / 128, 128>>>(centroids);

    const int grid = N / MTILE;  // 512
    const long long os = (long long)out_size;
    if (os == (long long)N * (D + 2) || os == (long long)N * (D / 2 + 1)) {
        vq_mma_kernel<1><<<grid, TPB, SMEM_TOTAL>>>(action, centroids, d_out, N);
    } else {
        vq_mma_kernel<0><<<grid, TPB, SMEM_TOTAL>>>(action, centroids, d_out, N);
    }
}

// round 16
// speedup vs baseline: 1.0545x; 1.0545x over previous
#include <cuda_runtime.h>
#include <cuda_fp16.h>
#include <cstdint>

#define D 64
#define KTOT 2048
#define MTILE 128
#define NCHUNK 64
#define NCHUNKS (KTOT / NCHUNK)   // 32
#define TPB 128                   // 4 warps, each owns an m32 slab

#define SAH 72            // A fp16 plane row stride (fp16; 144 B = 9*16, ldmatrix-aligned)
#define SBROW 68          // B smem row stride in uint2 (544 B)

#define OFF_AH 0
#define AH_BYTES (MTILE * SAH * 2)                // 18432
#define OFF_AL AH_BYTES                           // 18432
#define OFF_B0 (2 * AH_BYTES)                     // 36864
#define BSTRIDE (32 * SBROW * 8)                  // 17408 per buffer
#define OFF_HN0 (OFF_B0 + 2 * BSTRIDE)            // 71680 (2 x 256 B chunks)
#define OFF_BK (OFF_HN0 + 512)                    // 72192
#define SMEM_TOTAL (OFF_BK + MTILE * 4)           // 72704  (3 CTAs/SM)

// ---------------- device scratch (no runtime allocation) ----------------
__device__ float g_halfnorm[KTOT];
// [chunk(32)][kpair(32)][n(64)] -> (h0|h1<<16, l0|l1<<16)
__device__ __align__(16) uint2 g_bsplit[NCHUNKS * 32 * NCHUNK];

// ---------------- helpers ----------------
__device__ __forceinline__ uint32_t smem_u32(const void* p) {
    uint32_t a;
    asm("{ .reg .u64 t; cvta.to.shared.u64 t, %1; cvt.u32.u64 %0, t; }" : "=r"(a) : "l"(p));
    return a;
}
__device__ __forceinline__ void split_f16(float x, uint16_t& h, uint16_t& l) {
    __half hh = __float2half_rn(x);
    __half ll = __float2half_rn(x - __half2float(hh));
    h = __half_as_ushort(hh);
    l = __half_as_ushort(ll);
}
__device__ __forceinline__ void mma_f16(float& c0, float& c1, float& c2, float& c3,
                                        uint32_t a0, uint32_t a1, uint32_t a2, uint32_t a3,
                                        uint32_t b0, uint32_t b1) {
    asm volatile(
        "mma.sync.aligned.m16n8k16.row.col.f32.f16.f16.f32 "
        "{%0,%1,%2,%3}, {%4,%5,%6,%7}, {%8,%9}, {%0,%1,%2,%3};"
        : "+f"(c0), "+f"(c1), "+f"(c2), "+f"(c3)
        : "r"(a0), "r"(a1), "r"(a2), "r"(a3), "r"(b0), "r"(b1));
}
__device__ __forceinline__ void ldsm_x4(uint32_t& r0, uint32_t& r1, uint32_t& r2, uint32_t& r3,
                                        uint32_t addr) {
    asm volatile("ldmatrix.sync.aligned.m8n8.x4.shared.b16 {%0,%1,%2,%3}, [%4];"
                 : "=r"(r0), "=r"(r1), "=r"(r2), "=r"(r3) : "r"(addr));
}
#define CP_ASYNC16(dst, src) \
    asm volatile("cp.async.cg.shared.global [%0], [%1], 16;" :: "r"(dst), "l"(src) : "memory")
#define CP_COMMIT() asm volatile("cp.async.commit_group;" ::: "memory")
#define CP_WAIT1()  asm volatile("cp.async.wait_group 1;" ::: "memory")

// ---------------- fused prep kernel (halfnorm + fp16 h/l split) ----------------
__global__ void prep_kernel(const float* __restrict__ c) {
    int kc = blockIdx.x * blockDim.x + threadIdx.x;   // one centroid per thread
    if (kc >= KTOT) return;
    const int chunk = kc >> 6, n = kc & 63;
    uint2* dst = g_bsplit + chunk * (32 * NCHUNK) + n;
    float s = 0.f;
#pragma unroll
    for (int i = 0; i < D / 4; i++) {
        float4 v = ((const float4*)(c + (size_t)kc * D))[i];
        s += v.x * v.x + v.y * v.y + v.z * v.z + v.w * v.w;
        uint16_t h0, l0, h1, l1, h2, l2, h3, l3;
        split_f16(v.x, h0, l0); split_f16(v.y, h1, l1);
        split_f16(v.z, h2, l2); split_f16(v.w, h3, l3);
        dst[(2 * i) * NCHUNK]     = make_uint2((uint32_t)h0 | ((uint32_t)h1 << 16),
                                               (uint32_t)l0 | ((uint32_t)l1 << 16));
        dst[(2 * i + 1) * NCHUNK] = make_uint2((uint32_t)h2 | ((uint32_t)h3 << 16),
                                               (uint32_t)l2 | ((uint32_t)l3 << 16));
    }
    g_halfnorm[kc] = 0.5f * s;
}

// ---------------- main kernel ----------------
__device__ __forceinline__ void prefetch_chunk(uint32_t sbm, int buf, int ch, int tid) {
    // B: 32 rows x 64 uint2 = 16 KB = 1024 x 16B; smem row stride 544 B
    const char* src = (const char*)g_bsplit + (size_t)ch * 16384;
#pragma unroll
    for (int i = 0; i < 8; i++) {
        int idx = tid + i * TPB;           // 0..1023
        int r = idx >> 5, u = idx & 31;
        uint32_t dst = sbm + OFF_B0 + buf * BSTRIDE + r * (SBROW * 8) + u * 16;
        CP_ASYNC16(dst, src + r * 512 + u * 16);
    }
    // halfnorm slice for this chunk: 64 f32 = 256 B
    if (tid < 16) {
        CP_ASYNC16(sbm + OFF_HN0 + buf * 256 + tid * 16,
                   (const char*)g_halfnorm + (size_t)ch * 256 + tid * 16);
    }
}

template <int OutMode>
__global__ __launch_bounds__(TPB, 3) void vq_mma_kernel(
    const float* __restrict__ action, const float* __restrict__ centroids,
    void* __restrict__ out, int N) {
    extern __shared__ char smem[];
    const uint32_t sbm = smem_u32(smem);
    const int tid = threadIdx.x;
    const int w = tid >> 5;      // warp 0..3, owns rows [w*32, w*32+32)
    const int lane = tid & 31;
    const int g = lane >> 2;     // group id 0..7
    const int t = lane & 3;      // thread-in-group 0..3

    prefetch_chunk(sbm, 0, 0, tid);
    CP_COMMIT();
    prefetch_chunk(sbm, 1, 1, tid);
    CP_COMMIT();

    // stage A tile [128][64]: split fp32 -> fp16 h/l planes (stride SAH fp16)
    {
        const float4* src = (const float4*)(action + (size_t)blockIdx.x * MTILE * D);
#pragma unroll
        for (int i = 0; i < 16; i++) {
            int idx = tid + i * TPB;           // 2048 float4
            int r = idx >> 4, c4 = idx & 15;   // row, group of 4 cols
            float4 v = src[idx];
            uint16_t h0, l0, h1, l1, h2, l2, h3, l3;
            split_f16(v.x, h0, l0); split_f16(v.y, h1, l1);
            split_f16(v.z, h2, l2); split_f16(v.w, h3, l3);
            uint32_t off = (uint32_t)r * (SAH * 2) + (uint32_t)c4 * 8;
            *(uint2*)(smem + OFF_AH + off) =
                make_uint2((uint32_t)h0 | ((uint32_t)h1 << 16),
                           (uint32_t)h2 | ((uint32_t)h3 << 16));
            *(uint2*)(smem + OFF_AL + off) =
                make_uint2((uint32_t)l0 | ((uint32_t)l1 << 16),
                           (uint32_t)l2 | ((uint32_t)l3 << 16));
        }
    }
    __syncthreads();

    // ldmatrix base addresses (per s-slab, per plane); advance by 32B per ks.
    const int arow = w * 32 + (lane & 15);
    const uint32_t acol8 = ((lane >> 4) & 1) * 16;   // +8 fp16 = 16 B
    uint32_t aaddr[2][2];                            // [s][plane]
#pragma unroll
    for (int s = 0; s < 2; s++) {
        uint32_t rowoff = (uint32_t)(arow + s * 16) * (SAH * 2) + acol8;
        aaddr[s][0] = sbm + OFF_AH + rowoff;
        aaddr[s][1] = sbm + OFF_AL + rowoff;
    }

    // best per thread for rows w*32 + g + {0, 8, 16, 24}
    float best[4];
    int bk[4];
#pragma unroll
    for (int j = 0; j < 4; j++) { best[j] = -3.402823466e38f; bk[j] = 0; }

    const uint32_t browoff = (uint32_t)(t * SBROW + g) * 8;   // (kpair=t, n=g)

    for (int ch = 0; ch < NCHUNKS; ch++) {
        const int buf = ch & 1;
        CP_WAIT1();
        __syncthreads();
        const char* bbase = (const char*)smem + OFF_B0 + buf * BSTRIDE + browoff;
        const float* hn = (const float*)(smem + OFF_HN0 + buf * 256);

#pragma unroll
        for (int ng = 0; ng < 2; ng++) {
            // single accumulator set: hh + h*l + l*h accumulate here (fp32)
            float acc[4][8];
#pragma unroll
            for (int q = 0; q < 4; q++) {
                const int na = ng * 32 + q * 8 + 2 * t;
                const float h0 = hn[na], h1 = hn[na + 1];
#pragma unroll
                for (int s = 0; s < 2; s++) {
                    acc[q][s * 4 + 0] = -h0;
                    acc[q][s * 4 + 1] = -h1;
                    acc[q][s * 4 + 2] = -h0;
                    acc[q][s * 4 + 3] = -h1;
                }
            }

#pragma unroll
            for (int ks = 0; ks < 4; ks++) {
                uint32_t ah[2][4], al[2][4];
#pragma unroll
                for (int s = 0; s < 2; s++) {
                    ldsm_x4(ah[s][0], ah[s][1], ah[s][2], ah[s][3], aaddr[s][0] + ks * 32);
                    ldsm_x4(al[s][0], al[s][1], al[s][2], al[s][3], aaddr[s][1] + ks * 32);
                }
                uint2 u0[4], u1[4];
#pragma unroll
                for (int q = 0; q < 4; q++) {
                    const char* p0 = bbase + (uint32_t)ks * (8 * SBROW * 8) +
                                     (uint32_t)(ng * 32 + q * 8) * 8;
                    u0[q] = *(const uint2*)p0;                      // kpair 8ks+t
                    u1[q] = *(const uint2*)(p0 + 4 * SBROW * 8);    // kpair 8ks+t+4
                }
#pragma unroll
                for (int q = 0; q < 4; q++) {
#pragma unroll
                    for (int s = 0; s < 2; s++) {
                        mma_f16(acc[q][s*4+0], acc[q][s*4+1], acc[q][s*4+2], acc[q][s*4+3],
                                ah[s][0], ah[s][1], ah[s][2], ah[s][3], u0[q].x, u1[q].x);
                        mma_f16(acc[q][s*4+0], acc[q][s*4+1], acc[q][s*4+2], acc[q][s*4+3],
                                ah[s][0], ah[s][1], ah[s][2], ah[s][3], u0[q].y, u1[q].y);
                        mma_f16(acc[q][s*4+0], acc[q][s*4+1], acc[q][s*4+2], acc[q][s*4+3],
                                al[s][0], al[s][1], al[s][2], al[s][3], u0[q].x, u1[q].x);
                    }
                }
            }

            // argmax update (ascending n => strict '>' keeps earliest index)
#pragma unroll
            for (int q = 0; q < 4; q++) {
                const int na = ng * 32 + q * 8 + 2 * t;
                const int base = ch * NCHUNK;
#pragma unroll
                for (int s = 0; s < 2; s++) {
                    float s0 = acc[q][s*4+0];   // (row g+s*16,   na)
                    float s1 = acc[q][s*4+1];   // (row g+s*16,   na+1)
                    float s2 = acc[q][s*4+2];   // (row g+s*16+8, na)
                    float s3 = acc[q][s*4+3];   // (row g+s*16+8, na+1)
                    if (s0 > best[s*2+0]) { best[s*2+0] = s0; bk[s*2+0] = base + na; }
                    if (s1 > best[s*2+0]) { best[s*2+0] = s1; bk[s*2+0] = base + na + 1; }
                    if (s2 > best[s*2+1]) { best[s*2+1] = s2; bk[s*2+1] = base + na; }
                    if (s3 > best[s*2+1]) { best[s*2+1] = s3; bk[s*2+1] = base + na + 1; }
                }
            }
        }

        __syncthreads();
        {
            const int nxt = ch + 2;
            if (nxt < NCHUNKS) prefetch_chunk(sbm, nxt & 1, nxt, tid);
            CP_COMMIT();
        }
    }

    // quad reduction (over t), earliest index on ties
#pragma unroll
    for (int off = 1; off < 4; off <<= 1) {
#pragma unroll
        for (int j = 0; j < 4; j++) {
            float ob = __shfl_xor_sync(0xffffffffu, best[j], off);
            int ok = __shfl_xor_sync(0xffffffffu, bk[j], off);
            if (ob > best[j] || (ob == best[j] && ok < bk[j])) { best[j] = ob; bk[j] = ok; }
        }
    }
    if (t == 0) {
        int* sb = (int*)(smem + OFF_BK);
        sb[w * 32 + g]      = bk[0];
        sb[w * 32 + g + 8]  = bk[1];
        sb[w * 32 + g + 16] = bk[2];
        sb[w * 32 + g + 24] = bk[3];
    }
    __syncthreads();

    // epilogue (reload A from gmem; residual = a - c_best)
    const int* sbk = (const int*)(smem + OFF_BK);
    const int pbase = blockIdx.x * MTILE;
    const float4* asrc = (const float4*)(action + (size_t)pbase * D);
    if (OutMode == 1) {
        if (tid < MTILE) ((long long*)out)[pbase + tid] = (long long)sbk[tid];
        float* rbase = (float*)out + 2 * (size_t)N;
#pragma unroll
        for (int i = 0; i < 16; i++) {
            int idx = tid + i * TPB;
            int row = idx >> 4, c4 = idx & 15;
            float4 a = asrc[idx];
            float4 c = ((const float4*)(centroids + (size_t)sbk[row] * D))[c4];
            ((float4*)(rbase + (size_t)(pbase + row) * D))[c4] =
                make_float4(a.x - c.x, a.y - c.y, a.z - c.z, a.w - c.w);
        }
    } else {
        float* o = (float*)out;
        if (tid < MTILE) o[pbase + tid] = (float)sbk[tid];   // exact for K<=2048
        float* rbase = o + (size_t)N;
#pragma unroll
        for (int i = 0; i < 16; i++) {
            int idx = tid + i * TPB;
            int row = idx >> 4, c4 = idx & 15;
            float4 a = asrc[idx];
            float4 c = ((const float4*)(centroids + (size_t)sbk[row] * D))[c4];
            ((float4*)(rbase + (size_t)(pbase + row) * D))[c4] =
                make_float4(a.x - c.x, a.y - c.y, a.z - c.z, a.w - c.w);
        }
    }
}

// ---------------- launch ----------------
extern "C" void kernel_launch(void* const* d_in, const int* in_sizes, int n_in,
                              void* d_out, int out_size) {
    const float* action = (const float*)d_in[0];
    const float* centroids = (const float*)d_in[1];
    const int N = in_sizes[0] / D;   // 65536

    cudaFuncSetAttribute(vq_mma_kernel<0>, cudaFuncAttributeMaxDynamicSharedMemorySize, SMEM_TOTAL);
    cudaFuncSetAttribute(vq_mma_kernel<1>, cudaFuncAttributeMaxDynamicSharedMemorySize, SMEM_TOTAL);

    prep_kernel<<<(KTOT + 127) / 128, 128>>>(centroids);

    const int grid = N / MTILE;  // 512
    const long long os = (long long)out_size;
    if (os == (long long)N * (D + 2) || os == (long long)N * (D / 2 + 1)) {
        vq_mma_kernel<1><<<grid, TPB, SMEM_TOTAL>>>(action, centroids, d_out, N);
    } else {
        vq_mma_kernel<0><<<grid, TPB, SMEM_TOTAL>>>(action, centroids, d_out, N);
    }
}